// round 4
// baseline (speedup 1.0000x reference)
#include <cuda_runtime.h>
#include <cuda_bf16.h>

// Problem constants
#define BB   64      // batch (inputs)
#define MM   256     // modes
#define KK   4096    // spatial (64*64)

#define KC      64   // K per CTA chunk
#define KSPLIT  64   // KK / KC
#define MT      64   // modes per CTA (2 per lane)
#define MTILES  4    // MM / MT
#define NTHR    256  // 8 warps
#define KQ      (KC/4)   // float4 per row = 16
#define EPS_C   0.0009f

// Deterministic scratch (no cudaMalloc allowed)
__device__ __align__(16) float g_dot[KSPLIT * BB * MM];   // [s][b][m]  4 MB
__device__ __align__(16) float g_fss[KSPLIT * BB];        // [s][b]
__device__ __align__(16) float g_mss[KSPLIT * MM];        // [s][m]
__device__ unsigned int g_cnt[MTILES];                    // zero-init; reset by finalizer

__device__ __forceinline__ unsigned long long fma2(unsigned long long a,
                                                   unsigned long long b,
                                                   unsigned long long c) {
    unsigned long long d;
    asm("fma.rn.f32x2 %0, %1, %2, %3;" : "=l"(d) : "l"(a), "l"(b), "l"(c));
    return d;
}

__device__ __forceinline__ float2 ull2f2(unsigned long long u) {
    float2 f;
    f.x = __uint_as_float((unsigned int)u);
    f.y = __uint_as_float((unsigned int)(u >> 32));
    return f;
}

__device__ __forceinline__ float metric_of(float dot, float fss, float mss) {
    float fn = sqrtf(fss);
    float mn = sqrtf(mss);
    float cc = dot / (fn * mn);
    float dn = sqrtf(fmaxf(2.f - 2.f * cc, 0.f));
    float lum = (2.f * fn * mn + EPS_C) / (fss + mss + EPS_C);
    return (1.f - (2.f - dn) * 0.5f * sqrtf(lum)) * 2.f;
}

// CTA (mt, ks): partial dot[b=0..63][m = mt*64 .. +63] over k-chunk ks, plus
// partial norms. Last CTA per mt column reduces splits, computes the metric,
// atomicMin's into out (nonneg floats: uint order == float order).
__global__ __launch_bounds__(NTHR, 2)
void fused_kernel(const float* __restrict__ inp,
                  const float* __restrict__ mds,
                  unsigned int* __restrict__ outu) {
    __shared__ float As[BB * KC];    // 16 KB, k-major, unswizzled
    __shared__ float Bs[MT * KC];    // 16 KB, k-major, kq ^ (m&7) swizzle
    __shared__ float s_fss[BB];
    __shared__ float s_mss[MT];
    __shared__ int   s_flag;

    const int mt = blockIdx.x;
    const int ks = blockIdx.y;
    const int kbase = ks * KC;
    const int mbase = mt * MT;
    const int tid  = threadIdx.x;
    const int lane = tid & 31;
    const int w    = tid >> 5;       // 0..7

    float4* As4 = reinterpret_cast<float4*>(As);
    float4* Bs4 = reinterpret_cast<float4*>(Bs);

    // ---- stage A: 64 rows x 16 float4, coalesced ----
#pragma unroll
    for (int i = 0; i < 4; ++i) {
        int j  = i * NTHR + tid;
        int b  = j >> 4;
        int kq = j & 15;
        As4[b * KQ + kq] =
            *(reinterpret_cast<const float4*>(inp + (size_t)b * KK + kbase) + kq);
    }
    // ---- stage B: 64 rows x 16 float4, swizzled ----
#pragma unroll
    for (int i = 0; i < 4; ++i) {
        int j  = i * NTHR + tid;
        int m  = j >> 4;
        int kq = j & 15;
        Bs4[m * KQ + (kq ^ (m & 7))] =
            *(reinterpret_cast<const float4*>(mds + (size_t)(mbase + m) * KK + kbase) + kq);
    }
    __syncthreads();

    // ---- main loop: lane owns m=lane and m=lane+32; warp owns 8 b-rows ----
    const int c = lane & 7;          // swizzle const (same for lane and lane+32)
    const ulonglong2* As2 = reinterpret_cast<const ulonglong2*>(As);
    const ulonglong2* Bs2 = reinterpret_cast<const ulonglong2*>(Bs);

    unsigned long long acc[8][2];
#pragma unroll
    for (int r = 0; r < 8; ++r) { acc[r][0] = 0ull; acc[r][1] = 0ull; }

#pragma unroll 4
    for (int kq = 0; kq < KQ; ++kq) {
        ulonglong2 bv0 = Bs2[lane * KQ + (kq ^ c)];          // 4 phases
        ulonglong2 bv1 = Bs2[(lane + 32) * KQ + (kq ^ c)];   // 4 phases
#pragma unroll
        for (int r = 0; r < 8; ++r) {
            ulonglong2 av = As2[(8 * w + r) * KQ + kq];      // broadcast, 1 phase
            acc[r][0] = fma2(av.x, bv0.x, acc[r][0]);
            acc[r][0] = fma2(av.y, bv0.y, acc[r][0]);
            acc[r][1] = fma2(av.x, bv1.x, acc[r][1]);
            acc[r][1] = fma2(av.y, bv1.y, acc[r][1]);
        }
    }

    // ---- epilogue: coalesced partial-dot stores ----
#pragma unroll
    for (int r = 0; r < 8; ++r) {
        int b = 8 * w + r;
        float2 e0 = ull2f2(acc[r][0]);
        float2 e1 = ull2f2(acc[r][1]);
        g_dot[((size_t)ks * BB + b) * MM + mbase + lane]      = e0.x + e0.y;
        g_dot[((size_t)ks * BB + b) * MM + mbase + 32 + lane] = e1.x + e1.y;
    }

    // ---- partial squared norms (half-warp per row, 16 float4 per row) ----
    const int hk = lane & 15;        // float4 index within row
    const int hh = lane >> 4;        // half-warp id
#pragma unroll
    for (int r = 0; r < 4; ++r) {
        int m = 8 * w + 2 * r + hh;
        float4 v = Bs4[m * KQ + (hk ^ (m & 7))];
        float s = v.x * v.x + v.y * v.y + v.z * v.z + v.w * v.w;
#pragma unroll
        for (int o = 8; o > 0; o >>= 1) s += __shfl_xor_sync(0xffffffffu, s, o);
        if (hk == 0) g_mss[ks * MM + mbase + m] = s;
    }
    // input norms: every CTA writes bitwise-identical duplicates, so a column's
    // finalizer depends only on its own KSPLIT CTAs.
#pragma unroll
    for (int r = 0; r < 4; ++r) {
        int b = 8 * w + 2 * r + hh;
        float4 v = As4[b * KQ + hk];
        float s = v.x * v.x + v.y * v.y + v.z * v.z + v.w * v.w;
#pragma unroll
        for (int o = 8; o > 0; o >>= 1) s += __shfl_xor_sync(0xffffffffu, s, o);
        if (hk == 0) g_fss[ks * BB + b] = s;
    }

    // ---- last-CTA-per-column handoff ----
    __syncthreads();
    if (tid == 0) {
        __threadfence();
        unsigned int old = atomicAdd(&g_cnt[mt], 1u);
        s_flag = (old == KSPLIT - 1);
    }
    __syncthreads();
    if (!s_flag) return;
    __threadfence();

    // ---- finalize column mt: 64 b x 64 m ----
    if (tid < BB) {                  // summed input norms
        float s = 0.f;
#pragma unroll 8
        for (int ss = 0; ss < KSPLIT; ++ss) s += g_fss[ss * BB + tid];
        s_fss[tid] = s;
    } else if (tid < BB + MT) {      // summed mode norms for this column
        int m = tid - BB;
        float s = 0.f;
#pragma unroll 8
        for (int ss = 0; ss < KSPLIT; ++ss) s += g_mss[ss * MM + mbase + m];
        s_mss[m] = s;
    }
    __syncthreads();

    const float4* dot4 = reinterpret_cast<const float4*>(g_dot);

    // tasks: (b, m-quad). 64 b x 16 quads = 1024 tasks, 4 per thread.
#pragma unroll
    for (int i = 0; i < 4; ++i) {
        int task = tid + NTHR * i;
        int b = task >> 4;
        int q = task & 15;
        int col4 = (mbase >> 2) + q;

        float4 d = make_float4(0.f, 0.f, 0.f, 0.f);
#pragma unroll 8
        for (int ss = 0; ss < KSPLIT; ++ss) {
            float4 dv = dot4[((size_t)ss * BB + b) * (MM / 4) + col4];
            d.x += dv.x; d.y += dv.y; d.z += dv.z; d.w += dv.w;
        }
        float fss = s_fss[b];
        float v0 = metric_of(d.x, fss, s_mss[4 * q + 0]);
        float v1 = metric_of(d.y, fss, s_mss[4 * q + 1]);
        float v2 = metric_of(d.z, fss, s_mss[4 * q + 2]);
        float v3 = metric_of(d.w, fss, s_mss[4 * q + 3]);
        float v = fminf(fminf(v0, v1), fminf(v2, v3));
        atomicMin(&outu[b], __float_as_uint(v));
    }

    __syncthreads();
    if (tid == 0) g_cnt[mt] = 0;     // reset for next graph replay
}

extern "C" void kernel_launch(void* const* d_in, const int* in_sizes, int n_in,
                              void* d_out, int out_size) {
    const float* inp = (const float*)d_in[0];
    const float* mds = (const float*)d_in[1];
    if (in_sizes[0] > in_sizes[1]) {   // identify by element count
        const float* t = inp; inp = mds; mds = t;
    }

    // init out to +big positive (0x7f7f7f7f) for the atomicMin
    cudaMemsetAsync(d_out, 0x7f, (size_t)out_size * sizeof(float));

    dim3 grid(MTILES, KSPLIT);
    fused_kernel<<<grid, NTHR>>>(inp, mds, (unsigned int*)d_out);
}

// round 5
// speedup vs baseline: 2.0583x; 2.0583x over previous
#include <cuda_runtime.h>
#include <cuda_bf16.h>

// Problem constants
#define BB   64      // batch (inputs)
#define MM   256     // modes
#define KK   4096    // spatial (64*64)

#define KC      128  // K per CTA chunk
#define KSPLIT  32   // KK / KC
#define MT      32   // modes per CTA (one per lane)
#define MTILES  8    // MM / MT
#define EPS_C   0.0009f

// Deterministic partial buffers (no cudaMalloc allowed)
__device__ __align__(16) float g_dot[KSPLIT * BB * MM];   // [s][b][m]  2 MB
__device__ __align__(16) float g_fss[KSPLIT * BB];        // [s][b]
__device__ __align__(16) float g_mss[KSPLIT * MM];        // [s][m]

__device__ __forceinline__ unsigned long long fma2(unsigned long long a,
                                                   unsigned long long b,
                                                   unsigned long long c) {
    unsigned long long d;
    asm("fma.rn.f32x2 %0, %1, %2, %3;" : "=l"(d) : "l"(a), "l"(b), "l"(c));
    return d;
}

__device__ __forceinline__ float2 ull2f2(unsigned long long u) {
    float2 f;
    f.x = __uint_as_float((unsigned int)u);
    f.y = __uint_as_float((unsigned int)(u >> 32));
    return f;
}

// ===== GEMM (identical to the proven R2 kernel, plus d_out init writes) =====
// CTA (mt, ks): dot[b=0..63][m = mt*32 .. +31] over k-chunk ks.
__global__ __launch_bounds__(256, 2)
void gemm_partial_kernel(const float* __restrict__ inp,
                         const float* __restrict__ mds,
                         unsigned int* __restrict__ outu) {
    __shared__ float As[BB * KC];   // 32 KB, k-major, unswizzled
    __shared__ float Bs[MT * KC];   // 16 KB, k-major, kq ^ (m&7) swizzle

    const int mt = blockIdx.x;
    const int ks = blockIdx.y;
    const int kbase = ks * KC;
    const int mbase = mt * MT;
    const int tid  = threadIdx.x;
    const int lane = tid & 31;
    const int w    = tid >> 5;

    // init output for the finalize kernel's atomicMin (benign duplicate-free:
    // one CTA; stream order guarantees it lands before finalize runs)
    if (mt == 0 && ks == 0 && tid < BB) outu[tid] = 0x7f7f7f7fu;

    float4* As4 = reinterpret_cast<float4*>(As);
    float4* Bs4 = reinterpret_cast<float4*>(Bs);

    // ---- stage A: 64 rows x 32 float4, coalesced, no swizzle ----
#pragma unroll
    for (int i = 0; i < 8; ++i) {
        int j  = i * 256 + tid;
        int b  = j >> 5;
        int kq = j & 31;
        As4[b * 32 + kq] =
            *(reinterpret_cast<const float4*>(inp + (size_t)b * KK + kbase) + kq);
    }
    // ---- stage B: 32 rows x 32 float4, swizzled ----
#pragma unroll
    for (int i = 0; i < 4; ++i) {
        int j  = i * 256 + tid;
        int m  = j >> 5;
        int kq = j & 31;
        Bs4[m * 32 + (kq ^ (m & 7))] =
            *(reinterpret_cast<const float4*>(mds + (size_t)(mbase + m) * KK + kbase) + kq);
    }
    __syncthreads();

    // ---- main loop: lane's m fixed, 8 b-rows per warp, f32x2 over k-pairs ----
    const int c = lane & 7;
    const ulonglong2* As2 = reinterpret_cast<const ulonglong2*>(As);
    const ulonglong2* Bs2 = reinterpret_cast<const ulonglong2*>(Bs);

    unsigned long long acc[8];
#pragma unroll
    for (int r = 0; r < 8; ++r) acc[r] = 0ull;

#pragma unroll 4
    for (int kq = 0; kq < 32; ++kq) {
        ulonglong2 bv = Bs2[lane * 32 + (kq ^ c)];      // lane-distinct, 4 phases
#pragma unroll
        for (int r = 0; r < 8; ++r) {
            ulonglong2 av = As2[(8 * w + r) * 32 + kq]; // warp-broadcast
            acc[r] = fma2(av.x, bv.x, acc[r]);
            acc[r] = fma2(av.y, bv.y, acc[r]);
        }
    }

    // ---- epilogue: reduce k-parity lanes, coalesced store ----
#pragma unroll
    for (int r = 0; r < 8; ++r) {
        float2 e = ull2f2(acc[r]);
        g_dot[((size_t)ks * BB + 8 * w + r) * MM + mbase + lane] = e.x + e.y;
    }

    // ---- partial squared norms ----
#pragma unroll
    for (int r = 0; r < 4; ++r) {
        int m = 4 * w + r;
        float4 v = Bs4[m * 32 + (lane ^ (m & 7))];
        float s = v.x * v.x + v.y * v.y + v.z * v.z + v.w * v.w;
#pragma unroll
        for (int o = 16; o > 0; o >>= 1) s += __shfl_xor_sync(0xffffffffu, s, o);
        if (lane == 0) g_mss[ks * MM + mbase + m] = s;
    }
    if (mt == 0) {
#pragma unroll
        for (int r = 0; r < 8; ++r) {
            int b = 8 * w + r;
            float4 v = As4[b * 32 + lane];
            float s = v.x * v.x + v.y * v.y + v.z * v.z + v.w * v.w;
#pragma unroll
            for (int o = 16; o > 0; o >>= 1) s += __shfl_xor_sync(0xffffffffu, s, o);
            if (lane == 0) g_fss[ks * BB + b] = s;
        }
    }
}

// ===== Finalize: spread over 256 CTAs =====
// grid (BB, MM/64); block 256 = (64 modes) x (4 split-quarters).
// Thread sums 8 split-partials; 4-way smem combine; metric on sq==0 threads;
// warp-min; atomicMin into out (nonneg floats: uint order == float order).
__global__ __launch_bounds__(256)
void finalize_kernel(unsigned int* __restrict__ outu) {
    __shared__ float sd[4][64];
    __shared__ float sm_[4][64];
    __shared__ float sf[4];

    const int b  = blockIdx.x;
    const int mc = blockIdx.y;          // 0..3
    const int ml = threadIdx.x & 63;    // mode within chunk
    const int sq = threadIdx.x >> 6;    // split-quarter 0..3
    const int m  = mc * 64 + ml;

    float dot = 0.f, mss = 0.f, fss = 0.f;
#pragma unroll
    for (int i = 0; i < 8; ++i) {
        int s = sq * 8 + i;
        dot += g_dot[((size_t)s * BB + b) * MM + m];
        mss += g_mss[s * MM + m];
        fss += g_fss[s * BB + b];       // uniform across ml -> cache-served
    }
    sd[sq][ml]  = dot;
    sm_[sq][ml] = mss;
    if (ml == 0) sf[sq] = fss;
    __syncthreads();

    if (sq == 0) {
        dot = sd[0][ml] + sd[1][ml] + sd[2][ml] + sd[3][ml];
        mss = sm_[0][ml] + sm_[1][ml] + sm_[2][ml] + sm_[3][ml];
        fss = sf[0] + sf[1] + sf[2] + sf[3];

        float fn = sqrtf(fss);
        float mn = sqrtf(mss);
        float cc = dot / (fn * mn);
        float dn = sqrtf(fmaxf(2.f - 2.f * cc, 0.f));
        float lum = (2.f * fn * mn + EPS_C) / (fss + mss + EPS_C);
        float metric = (1.f - (2.f - dn) * 0.5f * sqrtf(lum)) * 2.f;

#pragma unroll
        for (int o = 16; o > 0; o >>= 1)
            metric = fminf(metric, __shfl_xor_sync(0xffffffffu, metric, o));
        if ((threadIdx.x & 31) == 0)
            atomicMin(&outu[b], __float_as_uint(metric));
    }
}

extern "C" void kernel_launch(void* const* d_in, const int* in_sizes, int n_in,
                              void* d_out, int out_size) {
    const float* inp = (const float*)d_in[0];
    const float* mds = (const float*)d_in[1];
    if (in_sizes[0] > in_sizes[1]) {   // identify by element count
        const float* t = inp; inp = mds; mds = t;
    }

    dim3 ggrid(MTILES, KSPLIT);
    gemm_partial_kernel<<<ggrid, 256>>>(inp, mds, (unsigned int*)d_out);

    dim3 fgrid(BB, MM / 64);
    finalize_kernel<<<fgrid, 256>>>((unsigned int*)d_out);
}